// round 11
// baseline (speedup 1.0000x reference)
#include <cuda_runtime.h>
#include <math.h>
#include <stdint.h>

// Problem constants
#define NB   2
#define NS   2048
#define ND   2048
#define NH   16
#define NDH  128
#define MROWS (NB*NS)        // 4096 flattened (b,s) rows
#define FEAT  (NH*NDH)       // 2048 flattened (h,e) features

// Scratch buffers (allocation-free rule: __device__ globals)
#define QKV_ELEMS 8388608ull  // 4096 * 2048
__device__ float g_q[QKV_ELEMS];
__device__ float g_k[QKV_ELEMS];
__device__ float g_v[QKV_ELEMS];
__device__ float g_z[QKV_ELEMS];

// ---------------------------------------------------------------------------
// tf32 helpers
// ---------------------------------------------------------------------------
__device__ __forceinline__ void split_tf32(float x, uint32_t& hi, uint32_t& lo)
{
    uint32_t h;
    asm("cvt.rna.tf32.f32 %0, %1;" : "=r"(h) : "f"(x));
    float r = x - __uint_as_float(h);
    asm("cvt.rna.tf32.f32 %0, %1;" : "=r"(lo) : "f"(r));
    hi = h;
}

__device__ __forceinline__ void mma_tf32(float* d, const uint32_t* a, const uint32_t* b)
{
    asm volatile(
        "mma.sync.aligned.m16n8k8.row.col.f32.tf32.tf32.f32 "
        "{%0,%1,%2,%3}, {%4,%5,%6,%7}, {%8,%9}, {%0,%1,%2,%3};\n"
        : "+f"(d[0]), "+f"(d[1]), "+f"(d[2]), "+f"(d[3])
        : "r"(a[0]), "r"(a[1]), "r"(a[2]), "r"(a[3]), "r"(b[0]), "r"(b[1]));
}

// Split a float4 into 4 (hi,lo) float2 pairs and store as two 16B writes.
// dst must be 16B-aligned (even float2 index).
__device__ __forceinline__ void st_split4(float2* dst, float4 v)
{
    uint32_t h0, l0, h1, l1, h2, l2, h3, l3;
    split_tf32(v.x, h0, l0); split_tf32(v.y, h1, l1);
    split_tf32(v.z, h2, l2); split_tf32(v.w, h3, l3);
    *(float4*)dst       = make_float4(__uint_as_float(h0), __uint_as_float(l0),
                                      __uint_as_float(h1), __uint_as_float(l1));
    *(float4*)(dst + 2) = make_float4(__uint_as_float(h2), __uint_as_float(l2),
                                      __uint_as_float(h3), __uint_as_float(l3));
}

// ---------------------------------------------------------------------------
// 3xTF32 GEMM with PRE-SPLIT smem tiles.
// C[4096 x 128-per-ntile] = A[4096 x K] * B + bias.
// Block 128x128, BK=16, 256 threads = 8 warps (2m x 4n), warp tile 64x32.
// Smem tiles hold (hi,lo) float2 per element, converted ONCE at load time;
// the inner loop is pure LDS.64 + MMA (tensor-bound).
// ---------------------------------------------------------------------------
#define BK2   16
#define AP2   20                      // A pitch in float2
#define BP2   132                     // B pitch in float2
#define A_F2  (128 * AP2)             // 2560 float2
#define B_F2  (BK2 * BP2)             // 2112 float2
#define BUF_F2 (A_F2 + B_F2)          // 4672 float2
#define GEMM2_SMEM (2 * BUF_F2 * 8)   // 74752 bytes

__device__ __forceinline__ void gemm_core_ps(
    const float* __restrict__ A, const float* __restrict__ B,
    const float* __restrict__ bias, float* __restrict__ C,
    int K, int lda, int ldb, long long btileStride, int ldc)
{
    extern __shared__ char smraw[];
    float2* sm2 = (float2*)smraw;

    const int tid  = threadIdx.x;
    const int lane = tid & 31;
    const int w    = tid >> 5;
    const int warpM = w >> 2;
    const int warpN = w & 3;
    const int g  = lane >> 2;
    const int tg = lane & 3;

    const int mtile = blockIdx.x, ntile = blockIdx.y;

    const float* Abase = A + (size_t)(mtile * 128) * lda;
    const float* Bbase = B + (size_t)ntile * btileStride;

    // gmem->smem mapping: A 512 float4 (2/thread), B 512 float4 (2/thread)
    const int am = tid >> 2;           // A row (0..63), +64 for second
    const int ak = (tid & 3) * 4;      // A col base
    const int bk = tid >> 5;           // B row (0..7), +8 for second
    const int bn = (tid & 31) * 4;     // B col base

    float acc[16][4];
#pragma unroll
    for (int i = 0; i < 16; i++)
#pragma unroll
        for (int j = 0; j < 4; j++) acc[i][j] = 0.0f;

    const int iters = K >> 4;

    float4 pa0, pa1, pb0, pb1;
    pa0 = *(const float4*)(Abase + (size_t)am * lda + ak);
    pa1 = *(const float4*)(Abase + (size_t)(am + 64) * lda + ak);
    pb0 = *(const float4*)(Bbase + (size_t)bk * ldb + bn);
    pb1 = *(const float4*)(Bbase + (size_t)(bk + 8) * ldb + bn);
    {
        float2* As2 = sm2;
        float2* Bs2 = sm2 + A_F2;
        st_split4(&As2[am * AP2 + ak], pa0);
        st_split4(&As2[(am + 64) * AP2 + ak], pa1);
        st_split4(&Bs2[bk * BP2 + bn], pb0);
        st_split4(&Bs2[(bk + 8) * BP2 + bn], pb1);
    }
    __syncthreads();

    int buf = 0;
    for (int kt = 0; kt < iters; kt++) {
        const bool more = (kt + 1 < iters);
        if (more) {
            const float* Ap = Abase + (size_t)(kt + 1) * BK2;
            const float* Bp = Bbase + (size_t)(kt + 1) * BK2 * ldb;
            pa0 = *(const float4*)(Ap + (size_t)am * lda + ak);
            pa1 = *(const float4*)(Ap + (size_t)(am + 64) * lda + ak);
            pb0 = *(const float4*)(Bp + (size_t)bk * ldb + bn);
            pb1 = *(const float4*)(Bp + (size_t)(bk + 8) * ldb + bn);
        }

        const float2* As2 = sm2 + buf * BUF_F2;
        const float2* Bs2 = As2 + A_F2;

#pragma unroll
        for (int ks = 0; ks < 2; ks++) {
            const int k0 = ks * 8;

            uint32_t bhi[4][2], blo[4][2];
#pragma unroll
            for (int nt = 0; nt < 4; nt++) {
                int n = warpN * 32 + nt * 8 + g;
                float2 f0 = Bs2[(k0 + tg) * BP2 + n];
                float2 f1 = Bs2[(k0 + tg + 4) * BP2 + n];
                bhi[nt][0] = __float_as_uint(f0.x); blo[nt][0] = __float_as_uint(f0.y);
                bhi[nt][1] = __float_as_uint(f1.x); blo[nt][1] = __float_as_uint(f1.y);
            }

#pragma unroll
            for (int mt = 0; mt < 4; mt++) {
                int m = warpM * 64 + mt * 16 + g;
                float2 a0 = As2[m * AP2 + k0 + tg];
                float2 a1 = As2[(m + 8) * AP2 + k0 + tg];
                float2 a2 = As2[m * AP2 + k0 + tg + 4];
                float2 a3 = As2[(m + 8) * AP2 + k0 + tg + 4];
                uint32_t ahi[4] = {__float_as_uint(a0.x), __float_as_uint(a1.x),
                                   __float_as_uint(a2.x), __float_as_uint(a3.x)};
                uint32_t alo[4] = {__float_as_uint(a0.y), __float_as_uint(a1.y),
                                   __float_as_uint(a2.y), __float_as_uint(a3.y)};
#pragma unroll
                for (int nt = 0; nt < 4; nt++) {
                    float* d = acc[mt * 4 + nt];
                    mma_tf32(d, ahi, bhi[nt]);
                    mma_tf32(d, ahi, blo[nt]);
                    mma_tf32(d, alo, bhi[nt]);
                }
            }
        }

        if (more) {
            float2* Ad = sm2 + (buf ^ 1) * BUF_F2;
            float2* Bd = Ad + A_F2;
            st_split4(&Ad[am * AP2 + ak], pa0);
            st_split4(&Ad[(am + 64) * AP2 + ak], pa1);
            st_split4(&Bd[bk * BP2 + bn], pb0);
            st_split4(&Bd[(bk + 8) * BP2 + bn], pb1);
            __syncthreads();
            buf ^= 1;
        }
    }

    // Epilogue: bias add + store
#pragma unroll
    for (int mt = 0; mt < 4; mt++) {
#pragma unroll
        for (int nt = 0; nt < 4; nt++) {
            const float* d = acc[mt * 4 + nt];
            int r0 = mtile * 128 + warpM * 64 + mt * 16 + g;
            int c  = ntile * 128 + warpN * 32 + nt * 8 + 2 * tg;
            float bx = bias[c], by = bias[c + 1];
            float2 lo = make_float2(d[0] + bx, d[1] + by);
            float2 hi = make_float2(d[2] + bx, d[3] + by);
            *(float2*)&C[(size_t)r0 * ldc + c]       = lo;
            *(float2*)&C[(size_t)(r0 + 8) * ldc + c] = hi;
        }
    }
}

// Fused QKV projections: grid.z selects which projection this CTA computes.
__global__ __launch_bounds__(256) void qkv_gemm_ps(
    const float* __restrict__ xq, const float* __restrict__ xk,
    const float* __restrict__ xv,
    const float* __restrict__ WQ, const float* __restrict__ WK,
    const float* __restrict__ WV,
    const float* __restrict__ bQ, const float* __restrict__ bK,
    const float* __restrict__ bV,
    float* __restrict__ q, float* __restrict__ k, float* __restrict__ v)
{
    const float *A, *B, *bias;
    float* C;
    if (blockIdx.z == 0)      { A = xq; B = WQ; bias = bQ; C = q; }
    else if (blockIdx.z == 1) { A = xk; B = WK; bias = bK; C = k; }
    else                      { A = xv; B = WV; bias = bV; C = v; }
    gemm_core_ps(A, B, bias, C, ND, ND, NDH, (long long)ND * NDH, FEAT);
}

__global__ __launch_bounds__(256) void out_gemm_ps(
    const float* __restrict__ A, const float* __restrict__ B,
    const float* __restrict__ bias, float* __restrict__ C)
{
    gemm_core_ps(A, B, bias, C, FEAT, FEAT, ND, 128LL, ND);
}

// ---------------------------------------------------------------------------
// Rotary (in-place on q and k). Unchanged.
// ---------------------------------------------------------------------------
__global__ void rotary_kernel(float* __restrict__ q, float* __restrict__ k)
{
    int p = blockIdx.x * blockDim.x + threadIdx.x;
    int e = p & 63;
    int h = (p >> 6) & 15;
    int s = (p >> 10) & 2047;
    int b = p >> 21;

    float freq = powf(10000.0f, (float)e * (1.0f / 64.0f));
    float ang  = (float)s / freq;
    float sn, cs;
    sincosf(ang, &sn, &cs);

    size_t base = ((size_t)(b * NS + s) * NH + h) * NDH + e;

    float x0 = q[base], x1 = q[base + 64];
    q[base]      = x0 * cs - x1 * sn;
    q[base + 64] = x1 * cs + x0 * sn;

    x0 = k[base]; x1 = k[base + 64];
    k[base]      = x0 * cs - x1 * sn;
    k[base + 64] = x1 * cs + x0 * sn;
}

// ---------------------------------------------------------------------------
// Flash attention, tensor cores, PRE-SPLIT K/V/P (3xTF32, causal).
// Br=128 rows/CTA, Bc=32 keys/tile, 256 threads = 8 warps x 16 rows.
// K,V split once per CTA into smem float2(hi,lo); P split once at write;
// Q stays unsplit in smem (on-the-fly split amortized over n-tiles).
// R10 FIX: K/V tile = 32 keys x 128 dims = 1024 float4 -> 4 float4/thread
// (R9 loaded only 2 -> keys 16..31 were garbage, rel_err 4.07).
// ---------------------------------------------------------------------------
#define FBC   32
#define FQP   132                       // Q pitch, f32
#define FKP   132                       // K/V pitch, f2
#define FPP   36                        // P pitch, f2
#define FQ_F32 (128 * FQP)              // 16896 floats
#define FK_F2  (FBC * FKP)              // 4224 f2
#define FP_F2  (16 * FPP)               // per-warp P: 576 f2
#define FLASH2_SMEM (FQ_F32 * 4 + (2 * FK_F2 + 8 * FP_F2) * 8)  // 172032 B

__global__ __launch_bounds__(256, 1) void flash_ps_kernel(
    const float* __restrict__ gq, const float* __restrict__ gk,
    const float* __restrict__ gv, float* __restrict__ gz)
{
    extern __shared__ char smraw[];
    float*  Qs  = (float*)smraw;
    float2* Ks2 = (float2*)(smraw + FQ_F32 * 4);
    float2* Vs2 = Ks2 + FK_F2;
    float2* Pbase = Vs2 + FK_F2;

    const int tid  = threadIdx.x;
    const int lane = tid & 31;
    const int w    = tid >> 5;
    const int g    = lane >> 2;
    const int tg   = lane & 3;
    const int qt   = blockIdx.x;      // 128-row query tile
    const int h    = blockIdx.y;
    const int b    = blockIdx.z;

    float2* Pw2 = Pbase + w * FP_F2;  // this warp's P buffer

    const size_t hb = (size_t)b * ((size_t)NS * NH * NDH) + (size_t)h * NDH;
    const float* qb = gq + hb;
    const float* kb = gk + hb;
    const float* vb = gv + hb;
    float* zb = gz + hb;

    const float scale = 0.08838834764831845f;   // 1/sqrt(128)
    const int ldrow = NH * NDH;                 // 2048

    // Load + pre-scale Q tile: 128 x 128
#pragma unroll
    for (int i = 0; i < 16; i++) {
        int idx = tid + 256 * i;
        int r = idx >> 5, c4 = idx & 31;
        float4 qv = *(const float4*)(qb + (size_t)(qt * 128 + r) * ldrow + c4 * 4);
        qv.x *= scale; qv.y *= scale; qv.z *= scale; qv.w *= scale;
        *(float4*)&Qs[r * FQP + c4 * 4] = qv;
    }

    float O[16][4];
#pragma unroll
    for (int i = 0; i < 16; i++)
#pragma unroll
        for (int j2 = 0; j2 < 4; j2++) O[i][j2] = 0.0f;
    float m0 = -INFINITY, m1 = -INFINITY, l0 = 0.0f, l1 = 0.0f;

    const int r0g = qt * 128 + w * 16 + g;
    const int r1g = r0g + 8;
    const int warp_rhi = qt * 128 + w * 16 + 15;
    const int jmax = 4 * qt + 3;

    for (int j = 0; j <= jmax; j++) {
        __syncthreads();
        // Load + split K,V tiles: 32 keys x 128 dims = 1024 float4 each
        // -> 4 float4 per thread per tensor (FIXED from 2)
#pragma unroll
        for (int i = 0; i < 4; i++) {
            int idx = tid + 256 * i;
            int r = idx >> 5, c4 = idx & 31;
            size_t gofs = (size_t)(j * FBC + r) * ldrow + c4 * 4;
            st_split4(&Ks2[r * FKP + c4 * 4], *(const float4*)(kb + gofs));
            st_split4(&Vs2[r * FKP + c4 * 4], *(const float4*)(vb + gofs));
        }
        __syncthreads();

        if (j * FBC > warp_rhi) continue;   // warp-uniform: fully masked tile

        // ---- S = Q K^T : sacc[4 nt][4], keys j*32..j*32+31 ----
        float sacc[4][4];
#pragma unroll
        for (int nt = 0; nt < 4; nt++)
#pragma unroll
            for (int v = 0; v < 4; v++) sacc[nt][v] = 0.0f;

#pragma unroll
        for (int ks = 0; ks < 16; ks++) {
            const int k0 = ks * 8;
            const int m = w * 16 + g;
            float a0 = Qs[m * FQP + k0 + tg];
            float a1 = Qs[(m + 8) * FQP + k0 + tg];
            float a2 = Qs[m * FQP + k0 + tg + 4];
            float a3 = Qs[(m + 8) * FQP + k0 + tg + 4];
            uint32_t ahi[4], alo[4];
            split_tf32(a0, ahi[0], alo[0]);
            split_tf32(a1, ahi[1], alo[1]);
            split_tf32(a2, ahi[2], alo[2]);
            split_tf32(a3, ahi[3], alo[3]);
#pragma unroll
            for (int nt = 0; nt < 4; nt++) {
                int n = nt * 8 + g;            // key within tile
                float2 f0 = Ks2[n * FKP + k0 + tg];
                float2 f1 = Ks2[n * FKP + k0 + tg + 4];
                uint32_t bhi[2] = {__float_as_uint(f0.x), __float_as_uint(f1.x)};
                uint32_t blo[2] = {__float_as_uint(f0.y), __float_as_uint(f1.y)};
                mma_tf32(sacc[nt], ahi, bhi);
                mma_tf32(sacc[nt], ahi, blo);
                mma_tf32(sacc[nt], alo, bhi);
            }
        }

        // ---- causal mask on diagonal tiles ----
        if (j * FBC + FBC - 1 > r0g) {
#pragma unroll
            for (int nt = 0; nt < 4; nt++) {
                int c = j * FBC + nt * 8 + 2 * tg;
                if (c > r0g)     sacc[nt][0] = -1e30f;
                if (c + 1 > r0g) sacc[nt][1] = -1e30f;
                if (c > r1g)     sacc[nt][2] = -1e30f;
                if (c + 1 > r1g) sacc[nt][3] = -1e30f;
            }
        }

        // ---- online softmax in accumulator layout ----
        float rmax0 = -1e30f, rmax1 = -1e30f;
#pragma unroll
        for (int nt = 0; nt < 4; nt++) {
            rmax0 = fmaxf(rmax0, fmaxf(sacc[nt][0], sacc[nt][1]));
            rmax1 = fmaxf(rmax1, fmaxf(sacc[nt][2], sacc[nt][3]));
        }
        rmax0 = fmaxf(rmax0, __shfl_xor_sync(0xffffffffu, rmax0, 1));
        rmax0 = fmaxf(rmax0, __shfl_xor_sync(0xffffffffu, rmax0, 2));
        rmax1 = fmaxf(rmax1, __shfl_xor_sync(0xffffffffu, rmax1, 1));
        rmax1 = fmaxf(rmax1, __shfl_xor_sync(0xffffffffu, rmax1, 2));

        float mn0 = fmaxf(m0, rmax0), mn1 = fmaxf(m1, rmax1);
        float alpha0 = __expf(m0 - mn0), alpha1 = __expf(m1 - mn1);

        float ps0 = 0.0f, ps1 = 0.0f;
#pragma unroll
        for (int nt = 0; nt < 4; nt++) {
            float p0 = __expf(sacc[nt][0] - mn0);
            float p1 = __expf(sacc[nt][1] - mn0);
            float p2 = __expf(sacc[nt][2] - mn1);
            float p3 = __expf(sacc[nt][3] - mn1);
            ps0 += p0 + p1;
            ps1 += p2 + p3;
            uint32_t h0, l0u, h1, l1u;
            split_tf32(p0, h0, l0u); split_tf32(p1, h1, l1u);
            *(float4*)&Pw2[g * FPP + nt * 8 + 2 * tg] =
                make_float4(__uint_as_float(h0), __uint_as_float(l0u),
                            __uint_as_float(h1), __uint_as_float(l1u));
            split_tf32(p2, h0, l0u); split_tf32(p3, h1, l1u);
            *(float4*)&Pw2[(g + 8) * FPP + nt * 8 + 2 * tg] =
                make_float4(__uint_as_float(h0), __uint_as_float(l0u),
                            __uint_as_float(h1), __uint_as_float(l1u));
        }
        ps0 += __shfl_xor_sync(0xffffffffu, ps0, 1);
        ps0 += __shfl_xor_sync(0xffffffffu, ps0, 2);
        ps1 += __shfl_xor_sync(0xffffffffu, ps1, 1);
        ps1 += __shfl_xor_sync(0xffffffffu, ps1, 2);

        l0 = l0 * alpha0 + ps0;  m0 = mn0;
        l1 = l1 * alpha1 + ps1;  m1 = mn1;

#pragma unroll
        for (int nt = 0; nt < 16; nt++) {
            O[nt][0] *= alpha0; O[nt][1] *= alpha0;
            O[nt][2] *= alpha1; O[nt][3] *= alpha1;
        }
        __syncwarp();   // P visible to whole warp

        // ---- O += P V ----
#pragma unroll
        for (int ks = 0; ks < 4; ks++) {
            const int k0 = ks * 8;
            float2 f;
            uint32_t ahi[4], alo[4];
            f = Pw2[g * FPP + k0 + tg];
            ahi[0] = __float_as_uint(f.x); alo[0] = __float_as_uint(f.y);
            f = Pw2[(g + 8) * FPP + k0 + tg];
            ahi[1] = __float_as_uint(f.x); alo[1] = __float_as_uint(f.y);
            f = Pw2[g * FPP + k0 + tg + 4];
            ahi[2] = __float_as_uint(f.x); alo[2] = __float_as_uint(f.y);
            f = Pw2[(g + 8) * FPP + k0 + tg + 4];
            ahi[3] = __float_as_uint(f.x); alo[3] = __float_as_uint(f.y);
#pragma unroll
            for (int nt = 0; nt < 16; nt++) {
                int n = nt * 8 + g;            // dim
                float2 f0 = Vs2[(k0 + tg) * FKP + n];
                float2 f1 = Vs2[(k0 + tg + 4) * FKP + n];
                uint32_t bhi[2] = {__float_as_uint(f0.x), __float_as_uint(f1.x)};
                uint32_t blo[2] = {__float_as_uint(f0.y), __float_as_uint(f1.y)};
                mma_tf32(O[nt], ahi, bhi);
                mma_tf32(O[nt], ahi, blo);
                mma_tf32(O[nt], alo, bhi);
            }
        }
        __syncwarp();   // P consumed before next tile overwrites it
    }

    // ---- epilogue: normalize and store ----
    float inv0 = 1.0f / l0, inv1 = 1.0f / l1;
#pragma unroll
    for (int nt = 0; nt < 16; nt++) {
        int c = nt * 8 + 2 * tg;
        *(float2*)&zb[(size_t)r0g * ldrow + c] =
            make_float2(O[nt][0] * inv0, O[nt][1] * inv0);
        *(float2*)&zb[(size_t)r1g * ldrow + c] =
            make_float2(O[nt][2] * inv1, O[nt][3] * inv1);
    }
}

// ---------------------------------------------------------------------------
// Launcher
// ---------------------------------------------------------------------------
extern "C" void kernel_launch(void* const* d_in, const int* in_sizes, int n_in,
                              void* d_out, int out_size)
{
    const float* xq = (const float*)d_in[0];
    const float* xk = (const float*)d_in[1];
    const float* xv = (const float*)d_in[2];
    const float* WQ = (const float*)d_in[3];
    const float* WK = (const float*)d_in[4];
    const float* WV = (const float*)d_in[5];
    const float* WO = (const float*)d_in[6];
    const float* bQ = (const float*)d_in[7];
    const float* bK = (const float*)d_in[8];
    const float* bV = (const float*)d_in[9];
    const float* bO = (const float*)d_in[10];
    float* out = (float*)d_out;

    float *qp, *kp, *vp, *zp;
    cudaGetSymbolAddress((void**)&qp, g_q);
    cudaGetSymbolAddress((void**)&kp, g_k);
    cudaGetSymbolAddress((void**)&vp, g_v);
    cudaGetSymbolAddress((void**)&zp, g_z);

    cudaFuncSetAttribute(qkv_gemm_ps,
                         cudaFuncAttributeMaxDynamicSharedMemorySize, GEMM2_SMEM);
    cudaFuncSetAttribute(out_gemm_ps,
                         cudaFuncAttributeMaxDynamicSharedMemorySize, GEMM2_SMEM);
    cudaFuncSetAttribute(flash_ps_kernel,
                         cudaFuncAttributeMaxDynamicSharedMemorySize, FLASH2_SMEM);

    // Fused QKV projections: 32 x 16 x 3 CTAs in one launch
    dim3 gqkv(MROWS / 128, FEAT / 128, 3);
    qkv_gemm_ps<<<gqkv, 256, GEMM2_SMEM>>>(xq, xk, xv, WQ, WK, WV,
                                           bQ, bK, bV, qp, kp, vp);

    // Rotary on q and k
    rotary_kernel<<<16384, 256>>>(qp, kp);

    // Flash attention (tensor cores, pre-split operands)
    flash_ps_kernel<<<dim3(NS / 128, NH, NB), 256, FLASH2_SMEM>>>(qp, kp, vp, zp);

    // Output projection
    dim3 gout(MROWS / 128, FEAT / 128);
    out_gemm_ps<<<gout, 256, GEMM2_SMEM>>>(zp, WO, bO, out);
}

// round 13
// speedup vs baseline: 1.1333x; 1.1333x over previous
#include <cuda_runtime.h>
#include <math.h>
#include <stdint.h>

// Problem constants
#define NB   2
#define NS   2048
#define ND   2048
#define NH   16
#define NDH  128
#define MROWS (NB*NS)        // 4096 flattened (b,s) rows
#define FEAT  (NH*NDH)       // 2048 flattened (h,e) features

// Scratch buffers (allocation-free rule: __device__ globals)
#define QKV_ELEMS 8388608ull  // 4096 * 2048
__device__ float g_q[QKV_ELEMS];
__device__ float g_k[QKV_ELEMS];
__device__ float g_v[QKV_ELEMS];
__device__ float g_z[QKV_ELEMS];

// ---------------------------------------------------------------------------
// tf32 helpers
// ---------------------------------------------------------------------------
__device__ __forceinline__ void split_tf32(float x, uint32_t& hi, uint32_t& lo)
{
    uint32_t h;
    asm("cvt.rna.tf32.f32 %0, %1;" : "=r"(h) : "f"(x));
    float r = x - __uint_as_float(h);
    asm("cvt.rna.tf32.f32 %0, %1;" : "=r"(lo) : "f"(r));
    hi = h;
}

__device__ __forceinline__ void mma_tf32(float* d, const uint32_t* a, const uint32_t* b)
{
    asm volatile(
        "mma.sync.aligned.m16n8k8.row.col.f32.tf32.tf32.f32 "
        "{%0,%1,%2,%3}, {%4,%5,%6,%7}, {%8,%9}, {%0,%1,%2,%3};\n"
        : "+f"(d[0]), "+f"(d[1]), "+f"(d[2]), "+f"(d[3])
        : "r"(a[0]), "r"(a[1]), "r"(a[2]), "r"(a[3]), "r"(b[0]), "r"(b[1]));
}

// Split a float4 into 4 (hi,lo) float2 pairs and store as two 16B writes.
// dst must be 16B-aligned (even float2 index).
__device__ __forceinline__ void st_split4(float2* dst, float4 v)
{
    uint32_t h0, l0, h1, l1, h2, l2, h3, l3;
    split_tf32(v.x, h0, l0); split_tf32(v.y, h1, l1);
    split_tf32(v.z, h2, l2); split_tf32(v.w, h3, l3);
    *(float4*)dst       = make_float4(__uint_as_float(h0), __uint_as_float(l0),
                                      __uint_as_float(h1), __uint_as_float(l1));
    *(float4*)(dst + 2) = make_float4(__uint_as_float(h2), __uint_as_float(l2),
                                      __uint_as_float(h3), __uint_as_float(l3));
}

// ---------------------------------------------------------------------------
// 3xTF32 GEMM with PRE-SPLIT smem tiles.
// C[4096 x 128-per-ntile] = A[4096 x K] * B + bias.
// Block 128x128, BK=16, 256 threads = 8 warps (2m x 4n), warp tile 64x32.
// Smem tiles hold (hi,lo) float2 per element, converted ONCE at load time;
// the inner loop is pure LDS.64 + MMA.
// __launch_bounds__(256, 2): R10's 132 regs broke 2-CTA residency
// (occ 12.5%, issue 45%); cap at 128 regs restores 2 CTAs/SM.
// ---------------------------------------------------------------------------
#define BK2   16
#define AP2   20                      // A pitch in float2
#define BP2   132                     // B pitch in float2
#define A_F2  (128 * AP2)             // 2560 float2
#define B_F2  (BK2 * BP2)             // 2112 float2
#define BUF_F2 (A_F2 + B_F2)          // 4672 float2
#define GEMM2_SMEM (2 * BUF_F2 * 8)   // 74752 bytes (x2 CTAs = 149.5KB <= 228KB)

__device__ __forceinline__ void gemm_core_ps(
    const float* __restrict__ A, const float* __restrict__ B,
    const float* __restrict__ bias, float* __restrict__ C,
    int K, int lda, int ldb, long long btileStride, int ldc)
{
    extern __shared__ char smraw[];
    float2* sm2 = (float2*)smraw;

    const int tid  = threadIdx.x;
    const int lane = tid & 31;
    const int w    = tid >> 5;
    const int warpM = w >> 2;
    const int warpN = w & 3;
    const int g  = lane >> 2;
    const int tg = lane & 3;

    const int mtile = blockIdx.x, ntile = blockIdx.y;

    const float* Abase = A + (size_t)(mtile * 128) * lda;
    const float* Bbase = B + (size_t)ntile * btileStride;

    // gmem->smem mapping: A 512 float4 (2/thread), B 512 float4 (2/thread)
    const int am = tid >> 2;           // A row (0..63), +64 for second
    const int ak = (tid & 3) * 4;      // A col base
    const int bk = tid >> 5;           // B row (0..7), +8 for second
    const int bn = (tid & 31) * 4;     // B col base

    float acc[16][4];
#pragma unroll
    for (int i = 0; i < 16; i++)
#pragma unroll
        for (int j = 0; j < 4; j++) acc[i][j] = 0.0f;

    const int iters = K >> 4;

    float4 pa0, pa1, pb0, pb1;
    pa0 = *(const float4*)(Abase + (size_t)am * lda + ak);
    pa1 = *(const float4*)(Abase + (size_t)(am + 64) * lda + ak);
    pb0 = *(const float4*)(Bbase + (size_t)bk * ldb + bn);
    pb1 = *(const float4*)(Bbase + (size_t)(bk + 8) * ldb + bn);
    {
        float2* As2 = sm2;
        float2* Bs2 = sm2 + A_F2;
        st_split4(&As2[am * AP2 + ak], pa0);
        st_split4(&As2[(am + 64) * AP2 + ak], pa1);
        st_split4(&Bs2[bk * BP2 + bn], pb0);
        st_split4(&Bs2[(bk + 8) * BP2 + bn], pb1);
    }
    __syncthreads();

    int buf = 0;
    for (int kt = 0; kt < iters; kt++) {
        const bool more = (kt + 1 < iters);
        if (more) {
            const float* Ap = Abase + (size_t)(kt + 1) * BK2;
            const float* Bp = Bbase + (size_t)(kt + 1) * BK2 * ldb;
            pa0 = *(const float4*)(Ap + (size_t)am * lda + ak);
            pa1 = *(const float4*)(Ap + (size_t)(am + 64) * lda + ak);
            pb0 = *(const float4*)(Bp + (size_t)bk * ldb + bn);
            pb1 = *(const float4*)(Bp + (size_t)(bk + 8) * ldb + bn);
        }

        const float2* As2 = sm2 + buf * BUF_F2;
        const float2* Bs2 = As2 + A_F2;

#pragma unroll
        for (int ks = 0; ks < 2; ks++) {
            const int k0 = ks * 8;

            uint32_t bhi[4][2], blo[4][2];
#pragma unroll
            for (int nt = 0; nt < 4; nt++) {
                int n = warpN * 32 + nt * 8 + g;
                float2 f0 = Bs2[(k0 + tg) * BP2 + n];
                float2 f1 = Bs2[(k0 + tg + 4) * BP2 + n];
                bhi[nt][0] = __float_as_uint(f0.x); blo[nt][0] = __float_as_uint(f0.y);
                bhi[nt][1] = __float_as_uint(f1.x); blo[nt][1] = __float_as_uint(f1.y);
            }

#pragma unroll
            for (int mt = 0; mt < 4; mt++) {
                int m = warpM * 64 + mt * 16 + g;
                float2 a0 = As2[m * AP2 + k0 + tg];
                float2 a1 = As2[(m + 8) * AP2 + k0 + tg];
                float2 a2 = As2[m * AP2 + k0 + tg + 4];
                float2 a3 = As2[(m + 8) * AP2 + k0 + tg + 4];
                uint32_t ahi[4] = {__float_as_uint(a0.x), __float_as_uint(a1.x),
                                   __float_as_uint(a2.x), __float_as_uint(a3.x)};
                uint32_t alo[4] = {__float_as_uint(a0.y), __float_as_uint(a1.y),
                                   __float_as_uint(a2.y), __float_as_uint(a3.y)};
#pragma unroll
                for (int nt = 0; nt < 4; nt++) {
                    float* d = acc[mt * 4 + nt];
                    mma_tf32(d, ahi, bhi[nt]);
                    mma_tf32(d, ahi, blo[nt]);
                    mma_tf32(d, alo, bhi[nt]);
                }
            }
        }

        if (more) {
            float2* Ad = sm2 + (buf ^ 1) * BUF_F2;
            float2* Bd = Ad + A_F2;
            st_split4(&Ad[am * AP2 + ak], pa0);
            st_split4(&Ad[(am + 64) * AP2 + ak], pa1);
            st_split4(&Bd[bk * BP2 + bn], pb0);
            st_split4(&Bd[(bk + 8) * BP2 + bn], pb1);
            __syncthreads();
            buf ^= 1;
        }
    }

    // Epilogue: bias add + store
#pragma unroll
    for (int mt = 0; mt < 4; mt++) {
#pragma unroll
        for (int nt = 0; nt < 4; nt++) {
            const float* d = acc[mt * 4 + nt];
            int r0 = mtile * 128 + warpM * 64 + mt * 16 + g;
            int c  = ntile * 128 + warpN * 32 + nt * 8 + 2 * tg;
            float bx = bias[c], by = bias[c + 1];
            float2 lo = make_float2(d[0] + bx, d[1] + by);
            float2 hi = make_float2(d[2] + bx, d[3] + by);
            *(float2*)&C[(size_t)r0 * ldc + c]       = lo;
            *(float2*)&C[(size_t)(r0 + 8) * ldc + c] = hi;
        }
    }
}

// Fused QKV projections: grid.z selects which projection this CTA computes.
__global__ __launch_bounds__(256, 2) void qkv_gemm_ps(
    const float* __restrict__ xq, const float* __restrict__ xk,
    const float* __restrict__ xv,
    const float* __restrict__ WQ, const float* __restrict__ WK,
    const float* __restrict__ WV,
    const float* __restrict__ bQ, const float* __restrict__ bK,
    const float* __restrict__ bV,
    float* __restrict__ q, float* __restrict__ k, float* __restrict__ v)
{
    const float *A, *B, *bias;
    float* C;
    if (blockIdx.z == 0)      { A = xq; B = WQ; bias = bQ; C = q; }
    else if (blockIdx.z == 1) { A = xk; B = WK; bias = bK; C = k; }
    else                      { A = xv; B = WV; bias = bV; C = v; }
    gemm_core_ps(A, B, bias, C, ND, ND, NDH, (long long)ND * NDH, FEAT);
}

__global__ __launch_bounds__(256, 2) void out_gemm_ps(
    const float* __restrict__ A, const float* __restrict__ B,
    const float* __restrict__ bias, float* __restrict__ C)
{
    gemm_core_ps(A, B, bias, C, FEAT, FEAT, ND, 128LL, ND);
}

// ---------------------------------------------------------------------------
// Rotary (in-place on q and k). Unchanged.
// ---------------------------------------------------------------------------
__global__ void rotary_kernel(float* __restrict__ q, float* __restrict__ k)
{
    int p = blockIdx.x * blockDim.x + threadIdx.x;
    int e = p & 63;
    int h = (p >> 6) & 15;
    int s = (p >> 10) & 2047;
    int b = p >> 21;

    float freq = powf(10000.0f, (float)e * (1.0f / 64.0f));
    float ang  = (float)s / freq;
    float sn, cs;
    sincosf(ang, &sn, &cs);

    size_t base = ((size_t)(b * NS + s) * NH + h) * NDH + e;

    float x0 = q[base], x1 = q[base + 64];
    q[base]      = x0 * cs - x1 * sn;
    q[base + 64] = x1 * cs + x0 * sn;

    x0 = k[base]; x1 = k[base + 64];
    k[base]      = x0 * cs - x1 * sn;
    k[base + 64] = x1 * cs + x0 * sn;
}

// ---------------------------------------------------------------------------
// Flash attention, tensor cores, PRE-SPLIT K/V/P (3xTF32, causal).
// Br=128 rows/CTA, Bc=32 keys/tile, 256 threads = 8 warps x 16 rows.
// Unchanged from R10 (improved flash to ~860us).
// ---------------------------------------------------------------------------
#define FBC   32
#define FQP   132                       // Q pitch, f32
#define FKP   132                       // K/V pitch, f2
#define FPP   36                        // P pitch, f2
#define FQ_F32 (128 * FQP)              // 16896 floats
#define FK_F2  (FBC * FKP)              // 4224 f2
#define FP_F2  (16 * FPP)               // per-warp P: 576 f2
#define FLASH2_SMEM (FQ_F32 * 4 + (2 * FK_F2 + 8 * FP_F2) * 8)  // 172032 B

__global__ __launch_bounds__(256, 1) void flash_ps_kernel(
    const float* __restrict__ gq, const float* __restrict__ gk,
    const float* __restrict__ gv, float* __restrict__ gz)
{
    extern __shared__ char smraw[];
    float*  Qs  = (float*)smraw;
    float2* Ks2 = (float2*)(smraw + FQ_F32 * 4);
    float2* Vs2 = Ks2 + FK_F2;
    float2* Pbase = Vs2 + FK_F2;

    const int tid  = threadIdx.x;
    const int lane = tid & 31;
    const int w    = tid >> 5;
    const int g    = lane >> 2;
    const int tg   = lane & 3;
    const int qt   = blockIdx.x;      // 128-row query tile
    const int h    = blockIdx.y;
    const int b    = blockIdx.z;

    float2* Pw2 = Pbase + w * FP_F2;  // this warp's P buffer

    const size_t hb = (size_t)b * ((size_t)NS * NH * NDH) + (size_t)h * NDH;
    const float* qb = gq + hb;
    const float* kb = gk + hb;
    const float* vb = gv + hb;
    float* zb = gz + hb;

    const float scale = 0.08838834764831845f;   // 1/sqrt(128)
    const int ldrow = NH * NDH;                 // 2048

    // Load + pre-scale Q tile: 128 x 128
#pragma unroll
    for (int i = 0; i < 16; i++) {
        int idx = tid + 256 * i;
        int r = idx >> 5, c4 = idx & 31;
        float4 qv = *(const float4*)(qb + (size_t)(qt * 128 + r) * ldrow + c4 * 4);
        qv.x *= scale; qv.y *= scale; qv.z *= scale; qv.w *= scale;
        *(float4*)&Qs[r * FQP + c4 * 4] = qv;
    }

    float O[16][4];
#pragma unroll
    for (int i = 0; i < 16; i++)
#pragma unroll
        for (int j2 = 0; j2 < 4; j2++) O[i][j2] = 0.0f;
    float m0 = -INFINITY, m1 = -INFINITY, l0 = 0.0f, l1 = 0.0f;

    const int r0g = qt * 128 + w * 16 + g;
    const int r1g = r0g + 8;
    const int warp_rhi = qt * 128 + w * 16 + 15;
    const int jmax = 4 * qt + 3;

    for (int j = 0; j <= jmax; j++) {
        __syncthreads();
        // Load + split K,V tiles: 32 keys x 128 dims = 1024 float4 each
#pragma unroll
        for (int i = 0; i < 4; i++) {
            int idx = tid + 256 * i;
            int r = idx >> 5, c4 = idx & 31;
            size_t gofs = (size_t)(j * FBC + r) * ldrow + c4 * 4;
            st_split4(&Ks2[r * FKP + c4 * 4], *(const float4*)(kb + gofs));
            st_split4(&Vs2[r * FKP + c4 * 4], *(const float4*)(vb + gofs));
        }
        __syncthreads();

        if (j * FBC > warp_rhi) continue;   // warp-uniform: fully masked tile

        // ---- S = Q K^T : sacc[4 nt][4], keys j*32..j*32+31 ----
        float sacc[4][4];
#pragma unroll
        for (int nt = 0; nt < 4; nt++)
#pragma unroll
            for (int v = 0; v < 4; v++) sacc[nt][v] = 0.0f;

#pragma unroll
        for (int ks = 0; ks < 16; ks++) {
            const int k0 = ks * 8;
            const int m = w * 16 + g;
            float a0 = Qs[m * FQP + k0 + tg];
            float a1 = Qs[(m + 8) * FQP + k0 + tg];
            float a2 = Qs[m * FQP + k0 + tg + 4];
            float a3 = Qs[(m + 8) * FQP + k0 + tg + 4];
            uint32_t ahi[4], alo[4];
            split_tf32(a0, ahi[0], alo[0]);
            split_tf32(a1, ahi[1], alo[1]);
            split_tf32(a2, ahi[2], alo[2]);
            split_tf32(a3, ahi[3], alo[3]);
#pragma unroll
            for (int nt = 0; nt < 4; nt++) {
                int n = nt * 8 + g;            // key within tile
                float2 f0 = Ks2[n * FKP + k0 + tg];
                float2 f1 = Ks2[n * FKP + k0 + tg + 4];
                uint32_t bhi[2] = {__float_as_uint(f0.x), __float_as_uint(f1.x)};
                uint32_t blo[2] = {__float_as_uint(f0.y), __float_as_uint(f1.y)};
                mma_tf32(sacc[nt], ahi, bhi);
                mma_tf32(sacc[nt], ahi, blo);
                mma_tf32(sacc[nt], alo, bhi);
            }
        }

        // ---- causal mask on diagonal tiles ----
        if (j * FBC + FBC - 1 > r0g) {
#pragma unroll
            for (int nt = 0; nt < 4; nt++) {
                int c = j * FBC + nt * 8 + 2 * tg;
                if (c > r0g)     sacc[nt][0] = -1e30f;
                if (c + 1 > r0g) sacc[nt][1] = -1e30f;
                if (c > r1g)     sacc[nt][2] = -1e30f;
                if (c + 1 > r1g) sacc[nt][3] = -1e30f;
            }
        }

        // ---- online softmax in accumulator layout ----
        float rmax0 = -1e30f, rmax1 = -1e30f;
#pragma unroll
        for (int nt = 0; nt < 4; nt++) {
            rmax0 = fmaxf(rmax0, fmaxf(sacc[nt][0], sacc[nt][1]));
            rmax1 = fmaxf(rmax1, fmaxf(sacc[nt][2], sacc[nt][3]));
        }
        rmax0 = fmaxf(rmax0, __shfl_xor_sync(0xffffffffu, rmax0, 1));
        rmax0 = fmaxf(rmax0, __shfl_xor_sync(0xffffffffu, rmax0, 2));
        rmax1 = fmaxf(rmax1, __shfl_xor_sync(0xffffffffu, rmax1, 1));
        rmax1 = fmaxf(rmax1, __shfl_xor_sync(0xffffffffu, rmax1, 2));

        float mn0 = fmaxf(m0, rmax0), mn1 = fmaxf(m1, rmax1);
        float alpha0 = __expf(m0 - mn0), alpha1 = __expf(m1 - mn1);

        float ps0 = 0.0f, ps1 = 0.0f;
#pragma unroll
        for (int nt = 0; nt < 4; nt++) {
            float p0 = __expf(sacc[nt][0] - mn0);
            float p1 = __expf(sacc[nt][1] - mn0);
            float p2 = __expf(sacc[nt][2] - mn1);
            float p3 = __expf(sacc[nt][3] - mn1);
            ps0 += p0 + p1;
            ps1 += p2 + p3;
            uint32_t h0, l0u, h1, l1u;
            split_tf32(p0, h0, l0u); split_tf32(p1, h1, l1u);
            *(float4*)&Pw2[g * FPP + nt * 8 + 2 * tg] =
                make_float4(__uint_as_float(h0), __uint_as_float(l0u),
                            __uint_as_float(h1), __uint_as_float(l1u));
            split_tf32(p2, h0, l0u); split_tf32(p3, h1, l1u);
            *(float4*)&Pw2[(g + 8) * FPP + nt * 8 + 2 * tg] =
                make_float4(__uint_as_float(h0), __uint_as_float(l0u),
                            __uint_as_float(h1), __uint_as_float(l1u));
        }
        ps0 += __shfl_xor_sync(0xffffffffu, ps0, 1);
        ps0 += __shfl_xor_sync(0xffffffffu, ps0, 2);
        ps1 += __shfl_xor_sync(0xffffffffu, ps1, 1);
        ps1 += __shfl_xor_sync(0xffffffffu, ps1, 2);

        l0 = l0 * alpha0 + ps0;  m0 = mn0;
        l1 = l1 * alpha1 + ps1;  m1 = mn1;

#pragma unroll
        for (int nt = 0; nt < 16; nt++) {
            O[nt][0] *= alpha0; O[nt][1] *= alpha0;
            O[nt][2] *= alpha1; O[nt][3] *= alpha1;
        }
        __syncwarp();   // P visible to whole warp

        // ---- O += P V ----
#pragma unroll
        for (int ks = 0; ks < 4; ks++) {
            const int k0 = ks * 8;
            float2 f;
            uint32_t ahi[4], alo[4];
            f = Pw2[g * FPP + k0 + tg];
            ahi[0] = __float_as_uint(f.x); alo[0] = __float_as_uint(f.y);
            f = Pw2[(g + 8) * FPP + k0 + tg];
            ahi[1] = __float_as_uint(f.x); alo[1] = __float_as_uint(f.y);
            f = Pw2[g * FPP + k0 + tg + 4];
            ahi[2] = __float_as_uint(f.x); alo[2] = __float_as_uint(f.y);
            f = Pw2[(g + 8) * FPP + k0 + tg + 4];
            ahi[3] = __float_as_uint(f.x); alo[3] = __float_as_uint(f.y);
#pragma unroll
            for (int nt = 0; nt < 16; nt++) {
                int n = nt * 8 + g;            // dim
                float2 f0 = Vs2[(k0 + tg) * FKP + n];
                float2 f1 = Vs2[(k0 + tg + 4) * FKP + n];
                uint32_t bhi[2] = {__float_as_uint(f0.x), __float_as_uint(f1.x)};
                uint32_t blo[2] = {__float_as_uint(f0.y), __float_as_uint(f1.y)};
                mma_tf32(O[nt], ahi, bhi);
                mma_tf32(O[nt], ahi, blo);
                mma_tf32(O[nt], alo, bhi);
            }
        }
        __syncwarp();   // P consumed before next tile overwrites it
    }

    // ---- epilogue: normalize and store ----
    float inv0 = 1.0f / l0, inv1 = 1.0f / l1;
#pragma unroll
    for (int nt = 0; nt < 16; nt++) {
        int c = nt * 8 + 2 * tg;
        *(float2*)&zb[(size_t)r0g * ldrow + c] =
            make_float2(O[nt][0] * inv0, O[nt][1] * inv0);
        *(float2*)&zb[(size_t)r1g * ldrow + c] =
            make_float2(O[nt][2] * inv1, O[nt][3] * inv1);
    }
}

// ---------------------------------------------------------------------------
// Launcher
// ---------------------------------------------------------------------------
extern "C" void kernel_launch(void* const* d_in, const int* in_sizes, int n_in,
                              void* d_out, int out_size)
{
    const float* xq = (const float*)d_in[0];
    const float* xk = (const float*)d_in[1];
    const float* xv = (const float*)d_in[2];
    const float* WQ = (const float*)d_in[3];
    const float* WK = (const float*)d_in[4];
    const float* WV = (const float*)d_in[5];
    const float* WO = (const float*)d_in[6];
    const float* bQ = (const float*)d_in[7];
    const float* bK = (const float*)d_in[8];
    const float* bV = (const float*)d_in[9];
    const float* bO = (const float*)d_in[10];
    float* out = (float*)d_out;

    float *qp, *kp, *vp, *zp;
    cudaGetSymbolAddress((void**)&qp, g_q);
    cudaGetSymbolAddress((void**)&kp, g_k);
    cudaGetSymbolAddress((void**)&vp, g_v);
    cudaGetSymbolAddress((void**)&zp, g_z);

    cudaFuncSetAttribute(qkv_gemm_ps,
                         cudaFuncAttributeMaxDynamicSharedMemorySize, GEMM2_SMEM);
    cudaFuncSetAttribute(out_gemm_ps,
                         cudaFuncAttributeMaxDynamicSharedMemorySize, GEMM2_SMEM);
    cudaFuncSetAttribute(flash_ps_kernel,
                         cudaFuncAttributeMaxDynamicSharedMemorySize, FLASH2_SMEM);

    // Fused QKV projections: 32 x 16 x 3 CTAs in one launch
    dim3 gqkv(MROWS / 128, FEAT / 128, 3);
    qkv_gemm_ps<<<gqkv, 256, GEMM2_SMEM>>>(xq, xk, xv, WQ, WK, WV,
                                           bQ, bK, bV, qp, kp, vp);

    // Rotary on q and k
    rotary_kernel<<<16384, 256>>>(qp, kp);

    // Flash attention (tensor cores, pre-split operands)
    flash_ps_kernel<<<dim3(NS / 128, NH, NB), 256, FLASH2_SMEM>>>(qp, kp, vp, zp);

    // Output projection
    dim3 gout(MROWS / 128, FEAT / 128);
    out_gemm_ps<<<gout, 256, GEMM2_SMEM>>>(zp, WO, bO, out);
}

// round 14
// speedup vs baseline: 1.4459x; 1.2759x over previous
#include <cuda_runtime.h>
#include <math.h>
#include <stdint.h>

// Problem constants
#define NB   2
#define NS   2048
#define ND   2048
#define NH   16
#define NDH  128
#define MROWS (NB*NS)        // 4096 flattened (b,s) rows
#define FEAT  (NH*NDH)       // 2048 flattened (h,e) features

// Scratch buffers (allocation-free rule: __device__ globals)
#define QKV_ELEMS 8388608ull  // 4096 * 2048
__device__ float g_q[QKV_ELEMS];
__device__ float g_k[QKV_ELEMS];
__device__ float g_v[QKV_ELEMS];
__device__ float g_z[QKV_ELEMS];

// ---------------------------------------------------------------------------
// tf32 helpers.
// split: hi = rna-rounded tf32 of x (1 cvt); lo = raw residual x-hi.
// Tensor core reads tf32 operands from the top 19 bits; the residual's own
// truncation contributes ~2^-25|x| — negligible vs the 3x-split error floor.
// ---------------------------------------------------------------------------
__device__ __forceinline__ void split_tf32(float x, uint32_t& hi, uint32_t& lo)
{
    uint32_t h;
    asm("cvt.rna.tf32.f32 %0, %1;" : "=r"(h) : "f"(x));
    lo = __float_as_uint(x - __uint_as_float(h));
    hi = h;
}

__device__ __forceinline__ void mma_tf32(float* d, const uint32_t* a, const uint32_t* b)
{
    asm volatile(
        "mma.sync.aligned.m16n8k8.row.col.f32.tf32.tf32.f32 "
        "{%0,%1,%2,%3}, {%4,%5,%6,%7}, {%8,%9}, {%0,%1,%2,%3};\n"
        : "+f"(d[0]), "+f"(d[1]), "+f"(d[2]), "+f"(d[3])
        : "r"(a[0]), "r"(a[1]), "r"(a[2]), "r"(a[3]), "r"(b[0]), "r"(b[1]));
}

__device__ __forceinline__ void cp16(uint32_t smem_addr, const void* gptr)
{
    asm volatile("cp.async.cg.shared.global [%0], [%1], 16;\n"
                 :: "r"(smem_addr), "l"(gptr));
}

// Split a float4 into 4 (hi,lo) float2 pairs, two 16B stores (flash K/V/P path).
__device__ __forceinline__ void st_split4(float2* dst, float4 v)
{
    uint32_t h0, l0, h1, l1, h2, l2, h3, l3;
    split_tf32(v.x, h0, l0); split_tf32(v.y, h1, l1);
    split_tf32(v.z, h2, l2); split_tf32(v.w, h3, l3);
    *(float4*)dst       = make_float4(__uint_as_float(h0), __uint_as_float(l0),
                                      __uint_as_float(h1), __uint_as_float(l1));
    *(float4*)(dst + 2) = make_float4(__uint_as_float(h2), __uint_as_float(l2),
                                      __uint_as_float(h3), __uint_as_float(l3));
}

// ---------------------------------------------------------------------------
// 3xTF32 tensor-core GEMM — R6 design (measured ~550us/GEMM), reverted from
// the pre-split experiment (R12: 797us; 2x LDS bytes beat the cvt savings).
// Block 128x128, BK=32, 256 threads = 8 warps (2m x 4n), warp tile 64x32.
// cp.async double-buffered raw-f32 smem; splits happen in registers.
// ---------------------------------------------------------------------------
#define BK      32
#define APITCH  36
#define BPITCH  136
#define A_SM    (128 * APITCH)
#define B_SM    (BK * BPITCH)
#define BUF_SM  (A_SM + B_SM)
#define GEMM_SMEM (2 * BUF_SM * 4)    // 71680 bytes (x2 CTAs = 143KB)

__device__ __forceinline__ void gemm_core(
    const float* __restrict__ A, const float* __restrict__ B,
    const float* __restrict__ bias, float* __restrict__ C,
    int K, int lda, int ldb, long long btileStride, int ldc)
{
    extern __shared__ float sm[];
    const uint32_t sm_u = (uint32_t)__cvta_generic_to_shared(sm);

    const int tid  = threadIdx.x;
    const int lane = tid & 31;
    const int w    = tid >> 5;
    const int warpM = w >> 2;
    const int warpN = w & 3;
    const int g  = lane >> 2;
    const int tg = lane & 3;

    const int mtile = blockIdx.x, ntile = blockIdx.y;

    const float* Abase = A + (size_t)(mtile * 128) * lda;
    const float* Bbase = B + (size_t)ntile * btileStride;

    const int a_kq = tid & 7;
    const int a_m0 = tid >> 3;
    const int b_n4 = tid & 31;
    const int b_k0 = tid >> 5;

    float acc[16][4];
#pragma unroll
    for (int i = 0; i < 16; i++)
#pragma unroll
        for (int j = 0; j < 4; j++) acc[i][j] = 0.0f;

    const int nt_iters = K >> 5;

#define ISSUE_TILE(kt, bf)                                                        \
    {                                                                             \
        uint32_t abuf = sm_u + (uint32_t)((bf) * BUF_SM) * 4u;                    \
        uint32_t bbuf = abuf + (uint32_t)A_SM * 4u;                               \
        _Pragma("unroll")                                                         \
        for (int i = 0; i < 4; i++) {                                             \
            int m = a_m0 + 32 * i;                                                \
            cp16(abuf + (uint32_t)(m * APITCH + a_kq * 4) * 4u,                   \
                 Abase + (size_t)m * lda + (kt) * BK + a_kq * 4);                 \
        }                                                                         \
        _Pragma("unroll")                                                         \
        for (int i = 0; i < 4; i++) {                                             \
            int k = b_k0 + 8 * i;                                                 \
            cp16(bbuf + (uint32_t)(k * BPITCH + b_n4 * 4) * 4u,                   \
                 Bbase + (size_t)((kt) * BK + k) * ldb + b_n4 * 4);               \
        }                                                                         \
        asm volatile("cp.async.commit_group;\n" ::);                              \
    }

    ISSUE_TILE(0, 0);

    int buf = 0;
    for (int kt = 0; kt < nt_iters; kt++) {
        if (kt + 1 < nt_iters) {
            ISSUE_TILE(kt + 1, buf ^ 1);
            asm volatile("cp.async.wait_group 1;\n" ::);
        } else {
            asm volatile("cp.async.wait_group 0;\n" ::);
        }
        __syncthreads();

        const float* Asb = sm + buf * BUF_SM;
        const float* Bsb = Asb + A_SM;

#pragma unroll
        for (int ks = 0; ks < 4; ks++) {
            const int k0 = ks * 8;

            uint32_t bhi[4][2], blo[4][2];
#pragma unroll
            for (int nt = 0; nt < 4; nt++) {
                int n = warpN * 32 + nt * 8 + g;
                float b0 = Bsb[(k0 + tg) * BPITCH + n];
                float b1 = Bsb[(k0 + tg + 4) * BPITCH + n];
                split_tf32(b0, bhi[nt][0], blo[nt][0]);
                split_tf32(b1, bhi[nt][1], blo[nt][1]);
            }

#pragma unroll
            for (int mt = 0; mt < 4; mt++) {
                int m = warpM * 64 + mt * 16 + g;
                float a0 = Asb[m * APITCH + k0 + tg];
                float a1 = Asb[(m + 8) * APITCH + k0 + tg];
                float a2 = Asb[m * APITCH + k0 + tg + 4];
                float a3 = Asb[(m + 8) * APITCH + k0 + tg + 4];
                uint32_t ahi[4], alo[4];
                split_tf32(a0, ahi[0], alo[0]);
                split_tf32(a1, ahi[1], alo[1]);
                split_tf32(a2, ahi[2], alo[2]);
                split_tf32(a3, ahi[3], alo[3]);
#pragma unroll
                for (int nt = 0; nt < 4; nt++) {
                    float* d = acc[mt * 4 + nt];
                    mma_tf32(d, ahi, bhi[nt]);
                    mma_tf32(d, ahi, blo[nt]);
                    mma_tf32(d, alo, bhi[nt]);
                }
            }
        }

        __syncthreads();
        buf ^= 1;
    }

    // Epilogue: bias add + store
#pragma unroll
    for (int mt = 0; mt < 4; mt++) {
#pragma unroll
        for (int nt = 0; nt < 4; nt++) {
            const float* d = acc[mt * 4 + nt];
            int r0 = mtile * 128 + warpM * 64 + mt * 16 + g;
            int c  = ntile * 128 + warpN * 32 + nt * 8 + 2 * tg;
            float bx = bias[c], by = bias[c + 1];
            float2 lo = make_float2(d[0] + bx, d[1] + by);
            float2 hi = make_float2(d[2] + bx, d[3] + by);
            *(float2*)&C[(size_t)r0 * ldc + c]       = lo;
            *(float2*)&C[(size_t)(r0 + 8) * ldc + c] = hi;
        }
    }
#undef ISSUE_TILE
}

// Fused QKV projections: grid.z selects which projection this CTA computes.
__global__ __launch_bounds__(256) void qkv_gemm(
    const float* __restrict__ xq, const float* __restrict__ xk,
    const float* __restrict__ xv,
    const float* __restrict__ WQ, const float* __restrict__ WK,
    const float* __restrict__ WV,
    const float* __restrict__ bQ, const float* __restrict__ bK,
    const float* __restrict__ bV,
    float* __restrict__ q, float* __restrict__ k, float* __restrict__ v)
{
    const float *A, *B, *bias;
    float* C;
    if (blockIdx.z == 0)      { A = xq; B = WQ; bias = bQ; C = q; }
    else if (blockIdx.z == 1) { A = xk; B = WK; bias = bK; C = k; }
    else                      { A = xv; B = WV; bias = bV; C = v; }
    gemm_core(A, B, bias, C, ND, ND, NDH, (long long)ND * NDH, FEAT);
}

__global__ __launch_bounds__(256) void out_gemm(
    const float* __restrict__ A, const float* __restrict__ B,
    const float* __restrict__ bias, float* __restrict__ C)
{
    gemm_core(A, B, bias, C, FEAT, FEAT, ND, 128LL, ND);
}

// ---------------------------------------------------------------------------
// Rotary (in-place on q and k). Unchanged.
// ---------------------------------------------------------------------------
__global__ void rotary_kernel(float* __restrict__ q, float* __restrict__ k)
{
    int p = blockIdx.x * blockDim.x + threadIdx.x;
    int e = p & 63;
    int h = (p >> 6) & 15;
    int s = (p >> 10) & 2047;
    int b = p >> 21;

    float freq = powf(10000.0f, (float)e * (1.0f / 64.0f));
    float ang  = (float)s / freq;
    float sn, cs;
    sincosf(ang, &sn, &cs);

    size_t base = ((size_t)(b * NS + s) * NH + h) * NDH + e;

    float x0 = q[base], x1 = q[base + 64];
    q[base]      = x0 * cs - x1 * sn;
    q[base + 64] = x1 * cs + x0 * sn;

    x0 = k[base]; x1 = k[base + 64];
    k[base]      = x0 * cs - x1 * sn;
    k[base + 64] = x1 * cs + x0 * sn;
}

// ---------------------------------------------------------------------------
// Flash attention, tensor cores, PRE-SPLIT K/V/P (3xTF32, causal).
// Br=128 rows/CTA, Bc=32 keys/tile, 256 threads = 8 warps x 16 rows.
// Unchanged from R10/R12 (measured ~860us; pre-split pays off here because
// K/V were being re-split redundantly by all 8 warps).
// ---------------------------------------------------------------------------
#define FBC   32
#define FQP   132                       // Q pitch, f32
#define FKP   132                       // K/V pitch, f2
#define FPP   36                        // P pitch, f2
#define FQ_F32 (128 * FQP)              // 16896 floats
#define FK_F2  (FBC * FKP)              // 4224 f2
#define FP_F2  (16 * FPP)               // per-warp P: 576 f2
#define FLASH2_SMEM (FQ_F32 * 4 + (2 * FK_F2 + 8 * FP_F2) * 8)  // 172032 B

__global__ __launch_bounds__(256, 1) void flash_ps_kernel(
    const float* __restrict__ gq, const float* __restrict__ gk,
    const float* __restrict__ gv, float* __restrict__ gz)
{
    extern __shared__ char smraw[];
    float*  Qs  = (float*)smraw;
    float2* Ks2 = (float2*)(smraw + FQ_F32 * 4);
    float2* Vs2 = Ks2 + FK_F2;
    float2* Pbase = Vs2 + FK_F2;

    const int tid  = threadIdx.x;
    const int lane = tid & 31;
    const int w    = tid >> 5;
    const int g    = lane >> 2;
    const int tg   = lane & 3;
    const int qt   = blockIdx.x;      // 128-row query tile
    const int h    = blockIdx.y;
    const int b    = blockIdx.z;

    float2* Pw2 = Pbase + w * FP_F2;  // this warp's P buffer

    const size_t hb = (size_t)b * ((size_t)NS * NH * NDH) + (size_t)h * NDH;
    const float* qb = gq + hb;
    const float* kb = gk + hb;
    const float* vb = gv + hb;
    float* zb = gz + hb;

    const float scale = 0.08838834764831845f;   // 1/sqrt(128)
    const int ldrow = NH * NDH;                 // 2048

    // Load + pre-scale Q tile: 128 x 128
#pragma unroll
    for (int i = 0; i < 16; i++) {
        int idx = tid + 256 * i;
        int r = idx >> 5, c4 = idx & 31;
        float4 qv = *(const float4*)(qb + (size_t)(qt * 128 + r) * ldrow + c4 * 4);
        qv.x *= scale; qv.y *= scale; qv.z *= scale; qv.w *= scale;
        *(float4*)&Qs[r * FQP + c4 * 4] = qv;
    }

    float O[16][4];
#pragma unroll
    for (int i = 0; i < 16; i++)
#pragma unroll
        for (int j2 = 0; j2 < 4; j2++) O[i][j2] = 0.0f;
    float m0 = -INFINITY, m1 = -INFINITY, l0 = 0.0f, l1 = 0.0f;

    const int r0g = qt * 128 + w * 16 + g;
    const int r1g = r0g + 8;
    const int warp_rhi = qt * 128 + w * 16 + 15;
    const int jmax = 4 * qt + 3;

    for (int j = 0; j <= jmax; j++) {
        __syncthreads();
        // Load + split K,V tiles: 32 keys x 128 dims = 1024 float4 each
#pragma unroll
        for (int i = 0; i < 4; i++) {
            int idx = tid + 256 * i;
            int r = idx >> 5, c4 = idx & 31;
            size_t gofs = (size_t)(j * FBC + r) * ldrow + c4 * 4;
            st_split4(&Ks2[r * FKP + c4 * 4], *(const float4*)(kb + gofs));
            st_split4(&Vs2[r * FKP + c4 * 4], *(const float4*)(vb + gofs));
        }
        __syncthreads();

        if (j * FBC > warp_rhi) continue;   // warp-uniform: fully masked tile

        // ---- S = Q K^T : sacc[4 nt][4], keys j*32..j*32+31 ----
        float sacc[4][4];
#pragma unroll
        for (int nt = 0; nt < 4; nt++)
#pragma unroll
            for (int v = 0; v < 4; v++) sacc[nt][v] = 0.0f;

#pragma unroll
        for (int ks = 0; ks < 16; ks++) {
            const int k0 = ks * 8;
            const int m = w * 16 + g;
            float a0 = Qs[m * FQP + k0 + tg];
            float a1 = Qs[(m + 8) * FQP + k0 + tg];
            float a2 = Qs[m * FQP + k0 + tg + 4];
            float a3 = Qs[(m + 8) * FQP + k0 + tg + 4];
            uint32_t ahi[4], alo[4];
            split_tf32(a0, ahi[0], alo[0]);
            split_tf32(a1, ahi[1], alo[1]);
            split_tf32(a2, ahi[2], alo[2]);
            split_tf32(a3, ahi[3], alo[3]);
#pragma unroll
            for (int nt = 0; nt < 4; nt++) {
                int n = nt * 8 + g;            // key within tile
                float2 f0 = Ks2[n * FKP + k0 + tg];
                float2 f1 = Ks2[n * FKP + k0 + tg + 4];
                uint32_t bhi[2] = {__float_as_uint(f0.x), __float_as_uint(f1.x)};
                uint32_t blo[2] = {__float_as_uint(f0.y), __float_as_uint(f1.y)};
                mma_tf32(sacc[nt], ahi, bhi);
                mma_tf32(sacc[nt], ahi, blo);
                mma_tf32(sacc[nt], alo, bhi);
            }
        }

        // ---- causal mask on diagonal tiles ----
        if (j * FBC + FBC - 1 > r0g) {
#pragma unroll
            for (int nt = 0; nt < 4; nt++) {
                int c = j * FBC + nt * 8 + 2 * tg;
                if (c > r0g)     sacc[nt][0] = -1e30f;
                if (c + 1 > r0g) sacc[nt][1] = -1e30f;
                if (c > r1g)     sacc[nt][2] = -1e30f;
                if (c + 1 > r1g) sacc[nt][3] = -1e30f;
            }
        }

        // ---- online softmax in accumulator layout ----
        float rmax0 = -1e30f, rmax1 = -1e30f;
#pragma unroll
        for (int nt = 0; nt < 4; nt++) {
            rmax0 = fmaxf(rmax0, fmaxf(sacc[nt][0], sacc[nt][1]));
            rmax1 = fmaxf(rmax1, fmaxf(sacc[nt][2], sacc[nt][3]));
        }
        rmax0 = fmaxf(rmax0, __shfl_xor_sync(0xffffffffu, rmax0, 1));
        rmax0 = fmaxf(rmax0, __shfl_xor_sync(0xffffffffu, rmax0, 2));
        rmax1 = fmaxf(rmax1, __shfl_xor_sync(0xffffffffu, rmax1, 1));
        rmax1 = fmaxf(rmax1, __shfl_xor_sync(0xffffffffu, rmax1, 2));

        float mn0 = fmaxf(m0, rmax0), mn1 = fmaxf(m1, rmax1);
        float alpha0 = __expf(m0 - mn0), alpha1 = __expf(m1 - mn1);

        float ps0 = 0.0f, ps1 = 0.0f;
#pragma unroll
        for (int nt = 0; nt < 4; nt++) {
            float p0 = __expf(sacc[nt][0] - mn0);
            float p1 = __expf(sacc[nt][1] - mn0);
            float p2 = __expf(sacc[nt][2] - mn1);
            float p3 = __expf(sacc[nt][3] - mn1);
            ps0 += p0 + p1;
            ps1 += p2 + p3;
            uint32_t h0, l0u, h1, l1u;
            split_tf32(p0, h0, l0u); split_tf32(p1, h1, l1u);
            *(float4*)&Pw2[g * FPP + nt * 8 + 2 * tg] =
                make_float4(__uint_as_float(h0), __uint_as_float(l0u),
                            __uint_as_float(h1), __uint_as_float(l1u));
            split_tf32(p2, h0, l0u); split_tf32(p3, h1, l1u);
            *(float4*)&Pw2[(g + 8) * FPP + nt * 8 + 2 * tg] =
                make_float4(__uint_as_float(h0), __uint_as_float(l0u),
                            __uint_as_float(h1), __uint_as_float(l1u));
        }
        ps0 += __shfl_xor_sync(0xffffffffu, ps0, 1);
        ps0 += __shfl_xor_sync(0xffffffffu, ps0, 2);
        ps1 += __shfl_xor_sync(0xffffffffu, ps1, 1);
        ps1 += __shfl_xor_sync(0xffffffffu, ps1, 2);

        l0 = l0 * alpha0 + ps0;  m0 = mn0;
        l1 = l1 * alpha1 + ps1;  m1 = mn1;

#pragma unroll
        for (int nt = 0; nt < 16; nt++) {
            O[nt][0] *= alpha0; O[nt][1] *= alpha0;
            O[nt][2] *= alpha1; O[nt][3] *= alpha1;
        }
        __syncwarp();   // P visible to whole warp

        // ---- O += P V ----
#pragma unroll
        for (int ks = 0; ks < 4; ks++) {
            const int k0 = ks * 8;
            float2 f;
            uint32_t ahi[4], alo[4];
            f = Pw2[g * FPP + k0 + tg];
            ahi[0] = __float_as_uint(f.x); alo[0] = __float_as_uint(f.y);
            f = Pw2[(g + 8) * FPP + k0 + tg];
            ahi[1] = __float_as_uint(f.x); alo[1] = __float_as_uint(f.y);
            f = Pw2[g * FPP + k0 + tg + 4];
            ahi[2] = __float_as_uint(f.x); alo[2] = __float_as_uint(f.y);
            f = Pw2[(g + 8) * FPP + k0 + tg + 4];
            ahi[3] = __float_as_uint(f.x); alo[3] = __float_as_uint(f.y);
#pragma unroll
            for (int nt = 0; nt < 16; nt++) {
                int n = nt * 8 + g;            // dim
                float2 f0 = Vs2[(k0 + tg) * FKP + n];
                float2 f1 = Vs2[(k0 + tg + 4) * FKP + n];
                uint32_t bhi[2] = {__float_as_uint(f0.x), __float_as_uint(f1.x)};
                uint32_t blo[2] = {__float_as_uint(f0.y), __float_as_uint(f1.y)};
                mma_tf32(O[nt], ahi, bhi);
                mma_tf32(O[nt], ahi, blo);
                mma_tf32(O[nt], alo, bhi);
            }
        }
        __syncwarp();   // P consumed before next tile overwrites it
    }

    // ---- epilogue: normalize and store ----
    float inv0 = 1.0f / l0, inv1 = 1.0f / l1;
#pragma unroll
    for (int nt = 0; nt < 16; nt++) {
        int c = nt * 8 + 2 * tg;
        *(float2*)&zb[(size_t)r0g * ldrow + c] =
            make_float2(O[nt][0] * inv0, O[nt][1] * inv0);
        *(float2*)&zb[(size_t)r1g * ldrow + c] =
            make_float2(O[nt][2] * inv1, O[nt][3] * inv1);
    }
}

// ---------------------------------------------------------------------------
// Launcher
// ---------------------------------------------------------------------------
extern "C" void kernel_launch(void* const* d_in, const int* in_sizes, int n_in,
                              void* d_out, int out_size)
{
    const float* xq = (const float*)d_in[0];
    const float* xk = (const float*)d_in[1];
    const float* xv = (const float*)d_in[2];
    const float* WQ = (const float*)d_in[3];
    const float* WK = (const float*)d_in[4];
    const float* WV = (const float*)d_in[5];
    const float* WO = (const float*)d_in[6];
    const float* bQ = (const float*)d_in[7];
    const float* bK = (const float*)d_in[8];
    const float* bV = (const float*)d_in[9];
    const float* bO = (const float*)d_in[10];
    float* out = (float*)d_out;

    float *qp, *kp, *vp, *zp;
    cudaGetSymbolAddress((void**)&qp, g_q);
    cudaGetSymbolAddress((void**)&kp, g_k);
    cudaGetSymbolAddress((void**)&vp, g_v);
    cudaGetSymbolAddress((void**)&zp, g_z);

    cudaFuncSetAttribute(qkv_gemm,
                         cudaFuncAttributeMaxDynamicSharedMemorySize, GEMM_SMEM);
    cudaFuncSetAttribute(out_gemm,
                         cudaFuncAttributeMaxDynamicSharedMemorySize, GEMM_SMEM);
    cudaFuncSetAttribute(flash_ps_kernel,
                         cudaFuncAttributeMaxDynamicSharedMemorySize, FLASH2_SMEM);

    // Fused QKV projections: 32 x 16 x 3 CTAs in one launch
    dim3 gqkv(MROWS / 128, FEAT / 128, 3);
    qkv_gemm<<<gqkv, 256, GEMM_SMEM>>>(xq, xk, xv, WQ, WK, WV,
                                       bQ, bK, bV, qp, kp, vp);

    // Rotary on q and k
    rotary_kernel<<<16384, 256>>>(qp, kp);

    // Flash attention (tensor cores, pre-split operands)
    flash_ps_kernel<<<dim3(NS / 128, NH, NB), 256, FLASH2_SMEM>>>(qp, kp, vp, zp);

    // Output projection
    dim3 gout(MROWS / 128, FEAT / 128);
    out_gemm<<<gout, 256, GEMM_SMEM>>>(zp, WO, bO, out);
}